// round 1
// baseline (speedup 1.0000x reference)
#include <cuda_runtime.h>
#include <cstddef>

#define BS 8
#define CLS 4
#define CCH 256
#define HH 128
#define WW 128
#define HW 16384
#define LL 19
#define TK 256
#define MH 64
#define MW 64

// Scratch (device globals: allocation is forbidden)
__device__ float g_U[BS][LL][TK];     // (t_q @ W1) / 16
__device__ float g_t3[BS][LL][CCH];   // token_s @ W3^T + b3
__device__ float g_a[BS][HW][20];     // softmaxed attention weights (19 used, padded to 20 for float4)

// ---------------------------------------------------------------------------
// prep: t_q = token_s @ W2^T ; U = (t_q @ W1) * (1/16) ; t3 = token_s @ W3^T + b3
// grid = BS blocks, 256 threads
// ---------------------------------------------------------------------------
__global__ void prep_kernel(const float* __restrict__ token_s,
                            const float* __restrict__ W1,
                            const float* __restrict__ W2,
                            const float* __restrict__ W3,
                            const float* __restrict__ b3) {
    int b = blockIdx.x;
    int t = threadIdx.x;
    __shared__ float tok[LL][TK];
    __shared__ float tq[LL][TK];
    for (int idx = t; idx < LL * TK; idx += blockDim.x)
        (&tok[0][0])[idx] = token_s[b * LL * TK + idx];
    __syncthreads();

    float acc[LL];
    // t_q[l][t] = sum_k tok[l][k] * W2[t][k]
#pragma unroll
    for (int l = 0; l < LL; l++) acc[l] = 0.f;
    for (int k = 0; k < TK; k++) {
        float w = W2[t * TK + k];
#pragma unroll
        for (int l = 0; l < LL; l++) acc[l] = fmaf(tok[l][k], w, acc[l]);
    }
#pragma unroll
    for (int l = 0; l < LL; l++) tq[l][t] = acc[l];
    __syncthreads();

    // U[l][c] = (1/16) * sum_t tq[l][t] * W1[t][c]    (c = this thread)
#pragma unroll
    for (int l = 0; l < LL; l++) acc[l] = 0.f;
    for (int k = 0; k < TK; k++) {
        float w = W1[k * CCH + t];
#pragma unroll
        for (int l = 0; l < LL; l++) acc[l] = fmaf(tq[l][k], w, acc[l]);
    }
#pragma unroll
    for (int l = 0; l < LL; l++) g_U[b][l][t] = acc[l] * 0.0625f;

    // t3[l][c] = sum_t tok[l][t] * W3[c][t] + b3[c]
#pragma unroll
    for (int l = 0; l < LL; l++) acc[l] = 0.f;
    for (int k = 0; k < TK; k++) {
        float w = W3[t * TK + k];
#pragma unroll
        for (int l = 0; l < LL; l++) acc[l] = fmaf(tok[l][k], w, acc[l]);
    }
    float bias = b3[t];
#pragma unroll
    for (int l = 0; l < LL; l++) g_t3[b][l][t] = acc[l] + bias;
}

// ---------------------------------------------------------------------------
// attn: per (b, n): a[l] = sum_c fea_c[b,c,n] * U[b,l,c], softmax over l,
//       zero where raw logit == 0, store to g_a.
// fea_c[b,c,n] = 0.25 * sum_cl mask_up[b,cl,n] * fea[(4b+cl)%8, c, n]
// grid = (BS, HW/256), 256 threads; b fastest so same-tile blocks across b
// run concurrently -> fea reuse hits L2.
// ---------------------------------------------------------------------------
__global__ void __launch_bounds__(256) attn_kernel(const float* __restrict__ mask,
                                                   const float* __restrict__ fea) {
    int b = blockIdx.x;
    int n = blockIdx.y * 256 + threadIdx.x;

    __shared__ float Us[LL][TK];
    for (int idx = threadIdx.x; idx < LL * TK; idx += 256)
        (&Us[0][0])[idx] = (&g_U[b][0][0])[idx];
    __syncthreads();

    int i = n >> 7, j = n & 127;
    int mi = i >> 1, mj = j >> 1;

    float m0, m1, m2, m3;
    const float *f0, *f1, *f2, *f3;
    {
        m0 = 0.25f * mask[((b * CLS + 0) * MH + mi) * MW + mj];
        m1 = 0.25f * mask[((b * CLS + 1) * MH + mi) * MW + mj];
        m2 = 0.25f * mask[((b * CLS + 2) * MH + mi) * MW + mj];
        m3 = 0.25f * mask[((b * CLS + 3) * MH + mi) * MW + mj];
        int s0 = (4 * b + 0) & 7, s1 = (4 * b + 1) & 7;
        int s2 = (4 * b + 2) & 7, s3 = (4 * b + 3) & 7;
        f0 = fea + (size_t)s0 * CCH * HW + n;
        f1 = fea + (size_t)s1 * CCH * HW + n;
        f2 = fea + (size_t)s2 * CCH * HW + n;
        f3 = fea + (size_t)s3 * CCH * HW + n;
    }

    float acc[LL];
#pragma unroll
    for (int l = 0; l < LL; l++) acc[l] = 0.f;

    for (int c = 0; c < CCH; c += 4) {
        float fc[4];
#pragma unroll
        for (int u = 0; u < 4; u++) {
            size_t off = (size_t)(c + u) * HW;
            float v = m0 * __ldg(&f0[off]);
            v = fmaf(m1, __ldg(&f1[off]), v);
            v = fmaf(m2, __ldg(&f2[off]), v);
            v = fmaf(m3, __ldg(&f3[off]), v);
            fc[u] = v;
        }
#pragma unroll
        for (int l = 0; l < LL; l++) {
            float4 uv = ((const float4*)Us[l])[c >> 2];
            acc[l] = fmaf(fc[0], uv.x, acc[l]);
            acc[l] = fmaf(fc[1], uv.y, acc[l]);
            acc[l] = fmaf(fc[2], uv.z, acc[l]);
            acc[l] = fmaf(fc[3], uv.w, acc[l]);
        }
    }

    // softmax over 19 logits (already scaled by 1/16 via U)
    float mx = acc[0];
#pragma unroll
    for (int l = 1; l < LL; l++) mx = fmaxf(mx, acc[l]);
    float e[LL];
    float sum = 0.f;
#pragma unroll
    for (int l = 0; l < LL; l++) { e[l] = __expf(acc[l] - mx); sum += e[l]; }
    float inv = 1.f / sum;

    float outv[20];
#pragma unroll
    for (int l = 0; l < LL; l++) outv[l] = (acc[l] != 0.f) ? e[l] * inv : 0.f;
    outv[19] = 0.f;

    float4* dst = (float4*)g_a[b][n];
#pragma unroll
    for (int q = 0; q < 5; q++) dst[q] = ((float4*)outv)[q];
}

// ---------------------------------------------------------------------------
// out: out[b,c,n] = fea[b,c,n] + sum_l a_soft[b,n,l] * t3[b,l,c]
// grid = (BS, HW/512), 256 threads, each thread handles 2 n positions.
// ---------------------------------------------------------------------------
__global__ void __launch_bounds__(256) out_kernel(const float* __restrict__ fea,
                                                  float* __restrict__ out) {
    int b = blockIdx.x;
    int n0 = blockIdx.y * 512;

    __shared__ float t3s[LL][CCH];
    for (int idx = threadIdx.x; idx < LL * CCH; idx += 256)
        (&t3s[0][0])[idx] = (&g_t3[b][0][0])[idx];
    __syncthreads();

    int n1 = n0 + threadIdx.x;
    int n2 = n1 + 256;

    float a1[20], a2[20];
#pragma unroll
    for (int q = 0; q < 5; q++) {
        ((float4*)a1)[q] = ((const float4*)g_a[b][n1])[q];
        ((float4*)a2)[q] = ((const float4*)g_a[b][n2])[q];
    }

    const float* fp = fea + (size_t)b * CCH * HW;
    float* op = out + (size_t)b * CCH * HW;

    for (int c4 = 0; c4 < CCH / 4; c4++) {
        float v1x = 0.f, v1y = 0.f, v1z = 0.f, v1w = 0.f;
        float v2x = 0.f, v2y = 0.f, v2z = 0.f, v2w = 0.f;
#pragma unroll
        for (int l = 0; l < LL; l++) {
            float4 t = ((const float4*)t3s[l])[c4];
            v1x = fmaf(a1[l], t.x, v1x);
            v1y = fmaf(a1[l], t.y, v1y);
            v1z = fmaf(a1[l], t.z, v1z);
            v1w = fmaf(a1[l], t.w, v1w);
            v2x = fmaf(a2[l], t.x, v2x);
            v2y = fmaf(a2[l], t.y, v2y);
            v2z = fmaf(a2[l], t.z, v2z);
            v2w = fmaf(a2[l], t.w, v2w);
        }
        size_t off0 = (size_t)(c4 * 4 + 0) * HW;
        size_t off1 = (size_t)(c4 * 4 + 1) * HW;
        size_t off2 = (size_t)(c4 * 4 + 2) * HW;
        size_t off3 = (size_t)(c4 * 4 + 3) * HW;
        op[off0 + n1] = fp[off0 + n1] + v1x;
        op[off1 + n1] = fp[off1 + n1] + v1y;
        op[off2 + n1] = fp[off2 + n1] + v1z;
        op[off3 + n1] = fp[off3 + n1] + v1w;
        op[off0 + n2] = fp[off0 + n2] + v2x;
        op[off1 + n2] = fp[off1 + n2] + v2y;
        op[off2 + n2] = fp[off2 + n2] + v2z;
        op[off3 + n2] = fp[off3 + n2] + v2w;
    }
}

extern "C" void kernel_launch(void* const* d_in, const int* in_sizes, int n_in,
                              void* d_out, int out_size) {
    const float* mask    = (const float*)d_in[0];
    const float* fea     = (const float*)d_in[1];
    const float* token_s = (const float*)d_in[2];
    const float* W1      = (const float*)d_in[3];
    const float* W2      = (const float*)d_in[4];
    const float* W3      = (const float*)d_in[5];
    const float* b3      = (const float*)d_in[6];
    float* out = (float*)d_out;

    prep_kernel<<<BS, 256>>>(token_s, W1, W2, W3, b3);
    attn_kernel<<<dim3(BS, HW / 256), 256>>>(mask, fea);
    out_kernel<<<dim3(BS, HW / 512), 256>>>(fea, out);
}

// round 2
// speedup vs baseline: 1.2969x; 1.2969x over previous
#include <cuda_runtime.h>
#include <cstddef>
#include <cstdint>

#define BS 8
#define CLS 4
#define CCH 256
#define HW 16384
#define LL 19
#define TK 256
#define MH 64
#define MW 64

// Scratch (device globals: allocation is forbidden)
__device__ float g_M[TK * CCH];       // M[k][c] = sum_t W2[t][k] * W1[t][c]
__device__ float g_W3T[TK * CCH];     // W3T[k][c] = W3[c][k]
__device__ float g_U[BS][LL][TK];     // (tok @ M) / 16
__device__ float g_t3[BS][LL][CCH];   // tok @ W3^T + b3
__device__ float g_a[BS][HW][20];     // softmaxed attn weights (19 used, padded)

// ---------------- f32x2 packed helpers (sm_103a) ----------------
__device__ __forceinline__ unsigned long long pk2(float lo, float hi) {
    unsigned long long r;
    asm("mov.b64 %0, {%1, %2};" : "=l"(r) : "f"(lo), "f"(hi));
    return r;
}
__device__ __forceinline__ void upk2(float& lo, float& hi, unsigned long long v) {
    asm("mov.b64 {%0, %1}, %2;" : "=f"(lo), "=f"(hi) : "l"(v));
}
__device__ __forceinline__ unsigned long long fma2(unsigned long long a,
                                                   unsigned long long b,
                                                   unsigned long long c) {
    unsigned long long d;
    asm("fma.rn.f32x2 %0, %1, %2, %3;" : "=l"(d) : "l"(a), "l"(b), "l"(c));
    return d;
}

// ---------------------------------------------------------------------------
// wprep: M[k][c] = sum_t W2[t][k]*W1[t][c]  and  W3T[k][c] = W3[c][k]
// grid = 32 (k-chunks of 8), 256 threads (c)
// ---------------------------------------------------------------------------
__global__ void __launch_bounds__(256) wprep_kernel(const float* __restrict__ W1,
                                                    const float* __restrict__ W2,
                                                    const float* __restrict__ W3) {
    int k0 = blockIdx.x * 8;
    int c = threadIdx.x;
    __shared__ float w2s[256][8];
    __shared__ float w3s[256][9];  // padded vs bank conflicts on transpose read
    for (int i = threadIdx.x; i < 2048; i += 256) {
        int r = i >> 3, j = i & 7;
        w2s[r][j] = W2[r * TK + k0 + j];
        w3s[r][j] = W3[r * TK + k0 + j];
    }
    __syncthreads();

    float acc[8];
#pragma unroll
    for (int j = 0; j < 8; j++) acc[j] = 0.f;
#pragma unroll 4
    for (int t = 0; t < 256; t++) {
        float w1 = W1[t * CCH + c];
#pragma unroll
        for (int j = 0; j < 8; j++) acc[j] = fmaf(w2s[t][j], w1, acc[j]);
    }
#pragma unroll
    for (int j = 0; j < 8; j++) {
        g_M[(k0 + j) * CCH + c] = acc[j];
        g_W3T[(k0 + j) * CCH + c] = w3s[c][j];
    }
}

// ---------------------------------------------------------------------------
// tokprep: U[b][l][c] = (1/16) sum_k tok[b][l][k]*M[k][c]
//          t3[b][l][c] = sum_k tok[b][l][k]*W3T[k][c] + b3[c]
// grid = (BS, 10): y/5 = phase (0:U, 1:t3), y%5 = l-group of 4 (last has 3)
// ---------------------------------------------------------------------------
__global__ void __launch_bounds__(256) tokprep_kernel(const float* __restrict__ token_s,
                                                      const float* __restrict__ b3) {
    int b = blockIdx.x;
    int y = blockIdx.y;
    int phase = y / 5;
    int l0 = (y % 5) * 4;
    int lcnt = (l0 + 4 <= LL) ? 4 : (LL - l0);
    int c = threadIdx.x;

    __shared__ float tok[4][256];
    for (int i = threadIdx.x; i < 4 * 256; i += 256) {
        int l = i >> 8, k = i & 255;
        tok[l][k] = (l < lcnt) ? token_s[(b * LL + l0 + l) * TK + k] : 0.f;
    }
    __syncthreads();

    const float* Mp = phase ? g_W3T : g_M;
    float acc[4] = {0.f, 0.f, 0.f, 0.f};
#pragma unroll 4
    for (int k = 0; k < 256; k++) {
        float m = Mp[k * CCH + c];
#pragma unroll
        for (int l = 0; l < 4; l++) acc[l] = fmaf(tok[l][k], m, acc[l]);
    }
    if (phase == 0) {
        for (int l = 0; l < lcnt; l++) g_U[b][l0 + l][c] = acc[l] * 0.0625f;
    } else {
        float bias = b3[c];
        for (int l = 0; l < lcnt; l++) g_t3[b][l0 + l][c] = acc[l] + bias;
    }
}

// ---------------------------------------------------------------------------
// attn2: packed f32x2, 2 batches + 2 pixels per thread.
// Groups: g0={0,2} g1={4,6} (sources 0..3), g2={1,3} g3={5,7} (sources 4..7).
// For each (b, n): logits[l] = sum_c fea_c[b,c,n] * U[b][l][c] (U has /16),
// softmax over l, zero where logit == 0, store to g_a.
// grid = (4, HW/512), 256 threads; pixels n1 = y*512+tid, n2 = n1+256.
// dynamic smem: Us2[2][19][256] of duplicated-pair u64 = 77824 B.
// ---------------------------------------------------------------------------
extern __shared__ unsigned long long Us2[];

__global__ void __launch_bounds__(256) attn2_kernel(const float* __restrict__ mask,
                                                    const float* __restrict__ fea) {
    int g = blockIdx.x;
    int b0 = (g < 2 ? 0 : 1) + (g & 1) * 4;
    int b1 = b0 + 2;
    int p = b0 & 1;  // source parity
    int tid = threadIdx.x;

    // stage U for the two batches, each value duplicated into an f32x2 pair
    for (int idx = tid; idx < 2 * LL * TK; idx += 256) {
        int bi = idx / (LL * TK);
        int rem = idx - bi * (LL * TK);
        int b = bi ? b1 : b0;
        float u = (&g_U[b][0][0])[rem];
        Us2[idx] = pk2(u, u);
    }
    __syncthreads();

    int n1 = blockIdx.y * 512 + tid;
    int n2 = n1 + 256;

    // mask coords: n = i*128+j ; nearest-down upsample 128->64: mi=i>>1, mj=j>>1
    int mi1 = (n1 >> 7) >> 1;
    int mi2 = ((n1 >> 7) + 2) >> 1;  // = mi1 + 1
    int mj = (n1 & 127) >> 1;

    unsigned long long mp[2][4];
#pragma unroll
    for (int bi = 0; bi < 2; bi++) {
        int b = bi ? b1 : b0;
#pragma unroll
        for (int s = 0; s < 4; s++) {
            float a1 = 0.25f * mask[((b * CLS + s) * MH + mi1) * MW + mj];
            float a2 = 0.25f * mask[((b * CLS + s) * MH + mi2) * MW + mj];
            mp[bi][s] = pk2(a1, a2);
        }
    }

    const float* fptr[4];
#pragma unroll
    for (int s = 0; s < 4; s++)
        fptr[s] = fea + (size_t)(4 * p + s) * CCH * HW;

    unsigned long long acc[2][LL];
#pragma unroll
    for (int bi = 0; bi < 2; bi++)
#pragma unroll
        for (int l = 0; l < LL; l++) acc[bi][l] = 0ULL;

    const unsigned long long* Up0 = Us2;
    const unsigned long long* Up1 = Us2 + LL * TK;

    for (int c = 0; c < CCH; c += 2) {
        unsigned long long fsA[4], fsB[4];
        size_t offA = (size_t)c * HW;
        size_t offB = offA + HW;
#pragma unroll
        for (int s = 0; s < 4; s++) {
            fsA[s] = pk2(__ldg(fptr[s] + offA + n1), __ldg(fptr[s] + offA + n2));
            fsB[s] = pk2(__ldg(fptr[s] + offB + n1), __ldg(fptr[s] + offB + n2));
        }
        unsigned long long cb0A = fma2(mp[0][0], fsA[0],
                                 fma2(mp[0][1], fsA[1],
                                 fma2(mp[0][2], fsA[2],
                                 fma2(mp[0][3], fsA[3], 0ULL))));
        unsigned long long cb1A = fma2(mp[1][0], fsA[0],
                                 fma2(mp[1][1], fsA[1],
                                 fma2(mp[1][2], fsA[2],
                                 fma2(mp[1][3], fsA[3], 0ULL))));
        unsigned long long cb0B = fma2(mp[0][0], fsB[0],
                                 fma2(mp[0][1], fsB[1],
                                 fma2(mp[0][2], fsB[2],
                                 fma2(mp[0][3], fsB[3], 0ULL))));
        unsigned long long cb1B = fma2(mp[1][0], fsB[0],
                                 fma2(mp[1][1], fsB[1],
                                 fma2(mp[1][2], fsB[2],
                                 fma2(mp[1][3], fsB[3], 0ULL))));
#pragma unroll
        for (int l = 0; l < LL; l++) {
            ulonglong2 u0 = *(const ulonglong2*)&Up0[l * TK + c];
            acc[0][l] = fma2(cb0A, u0.x, acc[0][l]);
            acc[0][l] = fma2(cb0B, u0.y, acc[0][l]);
            ulonglong2 u1 = *(const ulonglong2*)&Up1[l * TK + c];
            acc[1][l] = fma2(cb1A, u1.x, acc[1][l]);
            acc[1][l] = fma2(cb1B, u1.y, acc[1][l]);
        }
    }

    // epilogue: softmax per (batch, pixel), zero where raw logit == 0
#pragma unroll
    for (int bi = 0; bi < 2; bi++) {
        int b = bi ? b1 : b0;
        float lg1[LL], lg2[LL];
#pragma unroll
        for (int l = 0; l < LL; l++) upk2(lg1[l], lg2[l], acc[bi][l]);

#pragma unroll
        for (int px = 0; px < 2; px++) {
            const float* lg = px ? lg2 : lg1;
            int n = px ? n2 : n1;
            float mx = lg[0];
#pragma unroll
            for (int l = 1; l < LL; l++) mx = fmaxf(mx, lg[l]);
            float e[LL], sum = 0.f;
#pragma unroll
            for (int l = 0; l < LL; l++) { e[l] = __expf(lg[l] - mx); sum += e[l]; }
            float inv = 1.f / sum;
            float outv[20];
#pragma unroll
            for (int l = 0; l < LL; l++) outv[l] = (lg[l] != 0.f) ? e[l] * inv : 0.f;
            outv[19] = 0.f;
            float4* dst = (float4*)g_a[b][n];
#pragma unroll
            for (int q = 0; q < 5; q++) dst[q] = ((float4*)outv)[q];
        }
    }
}

// ---------------------------------------------------------------------------
// out: out[b,c,n] = fea[b,c,n] + sum_l a_soft[b,n,l] * t3[b,l,c]
// grid = (BS, HW/512), 256 threads, each thread handles 2 n positions.
// ---------------------------------------------------------------------------
__global__ void __launch_bounds__(256) out_kernel(const float* __restrict__ fea,
                                                  float* __restrict__ out) {
    int b = blockIdx.x;
    int n0 = blockIdx.y * 512;

    __shared__ float t3s[LL][CCH];
    for (int idx = threadIdx.x; idx < LL * CCH; idx += 256)
        (&t3s[0][0])[idx] = (&g_t3[b][0][0])[idx];
    __syncthreads();

    int n1 = n0 + threadIdx.x;
    int n2 = n1 + 256;

    float a1[20], a2[20];
#pragma unroll
    for (int q = 0; q < 5; q++) {
        ((float4*)a1)[q] = ((const float4*)g_a[b][n1])[q];
        ((float4*)a2)[q] = ((const float4*)g_a[b][n2])[q];
    }

    const float* fp = fea + (size_t)b * CCH * HW;
    float* op = out + (size_t)b * CCH * HW;

    for (int c4 = 0; c4 < CCH / 4; c4++) {
        float v1x = 0.f, v1y = 0.f, v1z = 0.f, v1w = 0.f;
        float v2x = 0.f, v2y = 0.f, v2z = 0.f, v2w = 0.f;
#pragma unroll
        for (int l = 0; l < LL; l++) {
            float4 t = ((const float4*)t3s[l])[c4];
            v1x = fmaf(a1[l], t.x, v1x);
            v1y = fmaf(a1[l], t.y, v1y);
            v1z = fmaf(a1[l], t.z, v1z);
            v1w = fmaf(a1[l], t.w, v1w);
            v2x = fmaf(a2[l], t.x, v2x);
            v2y = fmaf(a2[l], t.y, v2y);
            v2z = fmaf(a2[l], t.z, v2z);
            v2w = fmaf(a2[l], t.w, v2w);
        }
        size_t off0 = (size_t)(c4 * 4 + 0) * HW;
        size_t off1 = (size_t)(c4 * 4 + 1) * HW;
        size_t off2 = (size_t)(c4 * 4 + 2) * HW;
        size_t off3 = (size_t)(c4 * 4 + 3) * HW;
        op[off0 + n1] = fp[off0 + n1] + v1x;
        op[off1 + n1] = fp[off1 + n1] + v1y;
        op[off2 + n1] = fp[off2 + n1] + v1z;
        op[off3 + n1] = fp[off3 + n1] + v1w;
        op[off0 + n2] = fp[off0 + n2] + v2x;
        op[off1 + n2] = fp[off1 + n2] + v2y;
        op[off2 + n2] = fp[off2 + n2] + v2z;
        op[off3 + n2] = fp[off3 + n2] + v2w;
    }
}

extern "C" void kernel_launch(void* const* d_in, const int* in_sizes, int n_in,
                              void* d_out, int out_size) {
    const float* mask    = (const float*)d_in[0];
    const float* fea     = (const float*)d_in[1];
    const float* token_s = (const float*)d_in[2];
    const float* W1      = (const float*)d_in[3];
    const float* W2      = (const float*)d_in[4];
    const float* W3      = (const float*)d_in[5];
    const float* b3      = (const float*)d_in[6];
    float* out = (float*)d_out;

    static_assert(2 * LL * TK * sizeof(unsigned long long) == 77824, "smem size");
    cudaFuncSetAttribute(attn2_kernel, cudaFuncAttributeMaxDynamicSharedMemorySize, 77824);

    wprep_kernel<<<32, 256>>>(W1, W2, W3);
    tokprep_kernel<<<dim3(BS, 10), 256>>>(token_s, b3);
    attn2_kernel<<<dim3(4, HW / 512), 256, 77824>>>(mask, fea);
    out_kernel<<<dim3(BS, HW / 512), 256>>>(fea, out);
}

// round 3
// speedup vs baseline: 1.2999x; 1.0023x over previous
#include <cuda_runtime.h>
#include <cstddef>

#define BS 8
#define CLS 4
#define CCH 256
#define HW 16384
#define LL 19
#define TK 256
#define MH 64
#define MW 64

typedef unsigned long long u64;

// Scratch (device globals: allocation is forbidden)
__device__ float g_M[TK * CCH];       // M[k][c] = sum_t W2[t][k] * W1[t][c]
__device__ float g_W3T[TK * CCH];     // W3T[k][c] = W3[c][k]
__device__ float g_U[BS][LL][TK];     // (tok @ M) / 16
__device__ float g_t3[BS][LL][CCH];   // tok @ W3^T + b3
__device__ float g_a[BS][HW][20];     // softmaxed attn weights (19 used, padded)

// ---------------- f32x2 packed helpers (sm_103a) ----------------
__device__ __forceinline__ u64 pk2(float lo, float hi) {
    u64 r;
    asm("mov.b64 %0, {%1, %2};" : "=l"(r) : "f"(lo), "f"(hi));
    return r;
}
__device__ __forceinline__ void upk2(float& lo, float& hi, u64 v) {
    asm("mov.b64 {%0, %1}, %2;" : "=f"(lo), "=f"(hi) : "l"(v));
}
__device__ __forceinline__ u64 fma2(u64 a, u64 b, u64 c) {
    u64 d;
    asm("fma.rn.f32x2 %0, %1, %2, %3;" : "=l"(d) : "l"(a), "l"(b), "l"(c));
    return d;
}

// ---------------------------------------------------------------------------
// wprep: M[k][c] = sum_t W2[t][k]*W1[t][c]  and  W3T[k][c] = W3[c][k]
// grid = 64 (k-chunks of 4), 256 threads (c)
// ---------------------------------------------------------------------------
__global__ void __launch_bounds__(256) wprep_kernel(const float* __restrict__ W1,
                                                    const float* __restrict__ W2,
                                                    const float* __restrict__ W3) {
    int k0 = blockIdx.x * 4;
    int c = threadIdx.x;
    __shared__ float w2s[256][4];
    __shared__ float w3s[256][5];  // padded vs bank conflicts on transpose read
    for (int i = threadIdx.x; i < 1024; i += 256) {
        int r = i >> 2, j = i & 3;
        w2s[r][j] = W2[r * TK + k0 + j];
        w3s[r][j] = W3[r * TK + k0 + j];
    }
    __syncthreads();

    float acc[4] = {0.f, 0.f, 0.f, 0.f};
#pragma unroll 8
    for (int t = 0; t < 256; t++) {
        float w1 = W1[t * CCH + c];
#pragma unroll
        for (int j = 0; j < 4; j++) acc[j] = fmaf(w2s[t][j], w1, acc[j]);
    }
#pragma unroll
    for (int j = 0; j < 4; j++) {
        g_M[(k0 + j) * CCH + c] = acc[j];
        g_W3T[(k0 + j) * CCH + c] = w3s[c][j];
    }
}

// ---------------------------------------------------------------------------
// tokprep: U[b][l][c] = (1/16) sum_k tok[b][l][k]*M[k][c]
//          t3[b][l][c] = sum_k tok[b][l][k]*W3T[k][c] + b3[c]
// grid = (BS, 10): y/5 = phase (0:U, 1:t3), y%5 = l-group of 4 (last has 3)
// ---------------------------------------------------------------------------
__global__ void __launch_bounds__(256) tokprep_kernel(const float* __restrict__ token_s,
                                                      const float* __restrict__ b3) {
    int b = blockIdx.x;
    int y = blockIdx.y;
    int phase = y / 5;
    int l0 = (y % 5) * 4;
    int lcnt = (l0 + 4 <= LL) ? 4 : (LL - l0);
    int c = threadIdx.x;

    __shared__ float tok[4][256];
    for (int i = threadIdx.x; i < 4 * 256; i += 256) {
        int l = i >> 8, k = i & 255;
        tok[l][k] = (l < lcnt) ? token_s[(b * LL + l0 + l) * TK + k] : 0.f;
    }
    __syncthreads();

    const float* Mp = phase ? g_W3T : g_M;
    float acc[4] = {0.f, 0.f, 0.f, 0.f};
#pragma unroll 8
    for (int k = 0; k < 256; k++) {
        float m = Mp[k * CCH + c];
#pragma unroll
        for (int l = 0; l < 4; l++) acc[l] = fmaf(tok[l][k], m, acc[l]);
    }
    if (phase == 0) {
        for (int l = 0; l < lcnt; l++) g_U[b][l0 + l][c] = acc[l] * 0.0625f;
    } else {
        float bias = b3[c];
        for (int l = 0; l < lcnt; l++) g_t3[b][l0 + l][c] = acc[l] + bias;
    }
}

// ---------------------------------------------------------------------------
// attn3: f32x2 lanes = (even channel, odd channel). 2 batches per block.
// Groups g: 0:{0,2} 1:{4,6} (sources 0..3), 2:{1,3} 3:{5,7} (sources 4..7).
// logits[l] = sum_c fea_c[b,c,n] * U[b][l][c]  (U carries the 1/16),
// softmax over l, zero where raw logit == 0, store g_a.
// grid = (4, HW/128), 128 threads (1 px each). dyn smem = 2*19*256*4 = 38912 B.
// ---------------------------------------------------------------------------
extern __shared__ float Us[];  // [2][19][256] floats = [2][19][128] c-pairs

__global__ void __launch_bounds__(128) attn3_kernel(const float* __restrict__ mask,
                                                    const float* __restrict__ fea) {
    int g = blockIdx.x;
    int b0 = (g & 1) * 4 + (g >> 1);  // 0,4,1,5
    int b1 = b0 + 2;
    int p = g >> 1;                   // source parity
    int tid = threadIdx.x;

    for (int idx = tid; idx < 2 * LL * TK; idx += 128) {
        int bi = idx / (LL * TK);
        int rem = idx - bi * (LL * TK);
        Us[idx] = (&g_U[bi ? b1 : b0][0][0])[rem];
    }
    __syncthreads();

    int n = blockIdx.y * 128 + tid;
    int mi = blockIdx.y >> 1;  // row i = blockIdx.y, mi = i>>1
    int mj = tid >> 1;

    u64 mp[2][4];
#pragma unroll
    for (int bi = 0; bi < 2; bi++) {
        int b = bi ? b1 : b0;
#pragma unroll
        for (int s = 0; s < 4; s++) {
            float m = 0.25f * mask[((b * CLS + s) * MH + mi) * MW + mj];
            mp[bi][s] = pk2(m, m);
        }
    }

    const float* fp0 = fea + (size_t)(4 * p + 0) * CCH * HW + n;
    const float* fp1 = fea + (size_t)(4 * p + 1) * CCH * HW + n;
    const float* fp2 = fea + (size_t)(4 * p + 2) * CCH * HW + n;
    const float* fp3 = fea + (size_t)(4 * p + 3) * CCH * HW + n;

    u64 acc0[LL], acc1[LL];
#pragma unroll
    for (int l = 0; l < LL; l++) { acc0[l] = 0ULL; acc1[l] = 0ULL; }

    const u64* U0 = (const u64*)Us;             // [19][128]
    const u64* U1 = (const u64*)(Us + LL * TK);

#pragma unroll 2
    for (int cp = 0; cp < 128; cp++) {
        size_t offA = (size_t)(2 * cp) * HW;
        size_t offB = offA + HW;
        u64 fs0 = pk2(__ldg(fp0 + offA), __ldg(fp0 + offB));
        u64 fs1 = pk2(__ldg(fp1 + offA), __ldg(fp1 + offB));
        u64 fs2 = pk2(__ldg(fp2 + offA), __ldg(fp2 + offB));
        u64 fs3 = pk2(__ldg(fp3 + offA), __ldg(fp3 + offB));

        u64 cb0 = fma2(mp[0][3], fs3,
                  fma2(mp[0][2], fs2,
                  fma2(mp[0][1], fs1,
                  fma2(mp[0][0], fs0, 0ULL))));
        u64 cb1 = fma2(mp[1][3], fs3,
                  fma2(mp[1][2], fs2,
                  fma2(mp[1][1], fs1,
                  fma2(mp[1][0], fs0, 0ULL))));
#pragma unroll
        for (int l = 0; l < LL; l++) {
            acc0[l] = fma2(cb0, U0[l * 128 + cp], acc0[l]);
            acc1[l] = fma2(cb1, U1[l * 128 + cp], acc1[l]);
        }
    }

    // epilogue: softmax per (batch, pixel), zero where raw logit == 0
#pragma unroll
    for (int bi = 0; bi < 2; bi++) {
        int b = bi ? b1 : b0;
        float lg[LL];
#pragma unroll
        for (int l = 0; l < LL; l++) {
            float lo, hi;
            upk2(lo, hi, bi ? acc1[l] : acc0[l]);
            lg[l] = lo + hi;
        }
        float mx = lg[0];
#pragma unroll
        for (int l = 1; l < LL; l++) mx = fmaxf(mx, lg[l]);
        float e[LL], sum = 0.f;
#pragma unroll
        for (int l = 0; l < LL; l++) { e[l] = __expf(lg[l] - mx); sum += e[l]; }
        float inv = 1.f / sum;
        float outv[20];
#pragma unroll
        for (int l = 0; l < LL; l++) outv[l] = (lg[l] != 0.f) ? e[l] * inv : 0.f;
        outv[19] = 0.f;
        float4* dst = (float4*)g_a[b][n];
#pragma unroll
        for (int q = 0; q < 5; q++) dst[q] = ((float4*)outv)[q];
    }
}

// ---------------------------------------------------------------------------
// out2: out[b,c,n] = fea[b,c,n] + sum_l a[b,n,l] * t3[b,l,c]
// f32x2 lanes = (even channel, odd channel); t3 pair via broadcast LDS.64,
// a duplicated-packed per pixel in registers. 2 px/thread.
// grid = (BS, HW/512, 2 c-tiles of 128), 256 threads.
// ---------------------------------------------------------------------------
__global__ void __launch_bounds__(256) out2_kernel(const float* __restrict__ fea,
                                                   float* __restrict__ out) {
    int b = blockIdx.x;
    int c0 = blockIdx.z * 128;

    __shared__ float t3s[LL][128];
    for (int idx = threadIdx.x; idx < LL * 128; idx += 256) {
        int l = idx >> 7, c = idx & 127;
        t3s[l][c] = g_t3[b][l][c0 + c];
    }
    __syncthreads();

    int n1 = blockIdx.y * 512 + threadIdx.x;
    int n2 = n1 + 256;

    float a1[20], a2[20];
#pragma unroll
    for (int q = 0; q < 5; q++) {
        ((float4*)a1)[q] = ((const float4*)g_a[b][n1])[q];
        ((float4*)a2)[q] = ((const float4*)g_a[b][n2])[q];
    }
    u64 a1d[LL], a2d[LL];
#pragma unroll
    for (int l = 0; l < LL; l++) { a1d[l] = pk2(a1[l], a1[l]); a2d[l] = pk2(a2[l], a2[l]); }

    const float* fp = fea + (size_t)b * CCH * HW;
    float* op = out + (size_t)b * CCH * HW;
    const u64* t3p = (const u64*)&t3s[0][0];  // [19][64] c-pairs

#pragma unroll 2
    for (int cp = 0; cp < 64; cp++) {
        u64 v1 = 0ULL, v2 = 0ULL;
#pragma unroll
        for (int l = 0; l < LL; l++) {
            u64 t = t3p[l * 64 + cp];
            v1 = fma2(a1d[l], t, v1);
            v2 = fma2(a2d[l], t, v2);
        }
        float v1lo, v1hi, v2lo, v2hi;
        upk2(v1lo, v1hi, v1);
        upk2(v2lo, v2hi, v2);
        size_t offA = (size_t)(c0 + 2 * cp) * HW;
        size_t offB = offA + HW;
        op[offA + n1] = fp[offA + n1] + v1lo;
        op[offB + n1] = fp[offB + n1] + v1hi;
        op[offA + n2] = fp[offA + n2] + v2lo;
        op[offB + n2] = fp[offB + n2] + v2hi;
    }
}

extern "C" void kernel_launch(void* const* d_in, const int* in_sizes, int n_in,
                              void* d_out, int out_size) {
    const float* mask    = (const float*)d_in[0];
    const float* fea     = (const float*)d_in[1];
    const float* token_s = (const float*)d_in[2];
    const float* W1      = (const float*)d_in[3];
    const float* W2      = (const float*)d_in[4];
    const float* W3      = (const float*)d_in[5];
    const float* b3      = (const float*)d_in[6];
    float* out = (float*)d_out;

    wprep_kernel<<<64, 256>>>(W1, W2, W3);
    tokprep_kernel<<<dim3(BS, 10), 256>>>(token_s, b3);
    attn3_kernel<<<dim3(4, HW / 128), 128, 2 * LL * TK * sizeof(float)>>>(mask, fea);
    out2_kernel<<<dim3(BS, HW / 512, 2), 256>>>(fea, out);
}